// round 1
// baseline (speedup 1.0000x reference)
#include <cuda_runtime.h>
#include <math.h>

#define D 512
#define K 5
#define ROWS_PER_BLOCK 8
#define THREADS (ROWS_PER_BLOCK * 32)

// Precomputed: w[k][d] = alpha[d]*c[k][d], b[k] = sum_d alpha[d]*c[k][d]^2,
// sigw[k] = sigmoid(classif_w[k]). Static device scratch (no allocation).
__device__ float g_w[K * D];
__device__ float g_b[K];
__device__ float g_sigw[K];

__global__ void precompute_kernel(const float* __restrict__ alpha,
                                  const float* __restrict__ classif_w,
                                  const float* __restrict__ centroids) {
    int d = threadIdx.x;  // launched with D threads
    float a = alpha[d];
#pragma unroll
    for (int k = 0; k < K; k++) {
        g_w[k * D + d] = a * centroids[k * D + d];
    }
    // warp 0 computes b[k] deterministically (no atomics)
    if (threadIdx.x < 32) {
        int lane = threadIdx.x;
#pragma unroll
        for (int k = 0; k < K; k++) {
            float s = 0.f;
            for (int dd = lane; dd < D; dd += 32) {
                float c = centroids[k * D + dd];
                s += alpha[dd] * c * c;
            }
#pragma unroll
            for (int o = 16; o; o >>= 1) s += __shfl_xor_sync(0xffffffffu, s, o);
            if (lane == 0) g_b[k] = s;
        }
        if (lane < K) g_sigw[lane] = 1.0f / (1.0f + expf(-classif_w[lane]));
    }
}

__global__ __launch_bounds__(THREADS) void lfr_main_kernel(
    const float* __restrict__ x,
    const float* __restrict__ centroids,
    float* __restrict__ out_map,   // (N, K)
    float* __restrict__ out_rec,   // (N, D)
    float* __restrict__ out_pred,  // (N,)
    int n)
{
    __shared__ float s_c[K * D];   // raw centroids (for reconstruction)
    __shared__ float s_w[K * D];   // alpha-weighted centroids (for distance)
    __shared__ float s_b[K];
    __shared__ float s_sw[K];

    for (int i = threadIdx.x; i < K * D; i += THREADS) {
        s_c[i] = centroids[i];
        s_w[i] = g_w[i];
    }
    if (threadIdx.x < K) {
        s_b[threadIdx.x]  = g_b[threadIdx.x];
        s_sw[threadIdx.x] = g_sigw[threadIdx.x];
    }
    __syncthreads();

    const int warp = threadIdx.x >> 5;
    const int lane = threadIdx.x & 31;
    const int row  = blockIdx.x * ROWS_PER_BLOCK + warp;
    if (row >= n) return;

    // Load this row's x: 4 float4 per lane, fully coalesced, MLP=4
    const float4* xr = (const float4*)(x + (size_t)row * D);
    float4 xv[4];
#pragma unroll
    for (int i = 0; i < 4; i++) xv[i] = xr[i * 32 + lane];

    // 5 partial dot products vs smem w
    float dot[K];
#pragma unroll
    for (int k = 0; k < K; k++) dot[k] = 0.f;
#pragma unroll
    for (int i = 0; i < 4; i++) {
        const int d0 = (i * 32 + lane) * 4;
#pragma unroll
        for (int k = 0; k < K; k++) {
            const float4 w4 = *(const float4*)&s_w[k * D + d0];
            dot[k] += xv[i].x * w4.x + xv[i].y * w4.y +
                      xv[i].z * w4.z + xv[i].w * w4.w;
        }
    }
    // warp reduce each of the K dots
#pragma unroll
    for (int k = 0; k < K; k++) {
        float s = dot[k];
#pragma unroll
        for (int o = 16; o; o >>= 1) s += __shfl_xor_sync(0xffffffffu, s, o);
        dot[k] = s;
    }

    // softmax over shifted distances: dist'[k] = b[k] - 2*dot[k]
    // (the per-row constant sum_d alpha*x^2 cancels exactly after max-subtraction)
    float dist[K], m[K];
    float mx = -INFINITY;
#pragma unroll
    for (int k = 0; k < K; k++) {
        dist[k] = s_b[k] - 2.0f * dot[k];
        mx = fmaxf(mx, dist[k]);
    }
    float sum = 0.f;
#pragma unroll
    for (int k = 0; k < K; k++) {
        m[k] = expf(dist[k] - mx);
        sum += m[k];
    }
    const float inv = 1.0f / sum;
#pragma unroll
    for (int k = 0; k < K; k++) m[k] *= inv;

    // mapping
    if (lane < K) out_map[(size_t)row * K + lane] = m[lane];
    // pred
    if (lane == 0) {
        float p = 0.f;
#pragma unroll
        for (int k = 0; k < K; k++) p += m[k] * s_sw[k];
        out_pred[row] = p;
    }
    // reconstructed = mapping @ centroids
    float4* rr = (float4*)(out_rec + (size_t)row * D);
#pragma unroll
    for (int i = 0; i < 4; i++) {
        const int d0 = (i * 32 + lane) * 4;
        float4 r = make_float4(0.f, 0.f, 0.f, 0.f);
#pragma unroll
        for (int k = 0; k < K; k++) {
            const float4 c4 = *(const float4*)&s_c[k * D + d0];
            r.x += m[k] * c4.x;
            r.y += m[k] * c4.y;
            r.z += m[k] * c4.z;
            r.w += m[k] * c4.w;
        }
        rr[i * 32 + lane] = r;
    }
}

extern "C" void kernel_launch(void* const* d_in, const int* in_sizes, int n_in,
                              void* d_out, int out_size) {
    // metadata order: x, is_protected, alpha_p, classif_w, centroids
    const float* x      = (const float*)d_in[0];
    const float* alpha  = (const float*)d_in[2];
    const float* cw     = (const float*)d_in[3];
    const float* cent   = (const float*)d_in[4];
    const int n = in_sizes[1];  // element count of is_protected == N

    float* out      = (float*)d_out;
    float* out_map  = out;                          // N*K
    float* out_rec  = out + (size_t)n * K;          // N*D
    float* out_pred = out_rec + (size_t)n * D;      // N

    precompute_kernel<<<1, D>>>(alpha, cw, cent);
    lfr_main_kernel<<<(n + ROWS_PER_BLOCK - 1) / ROWS_PER_BLOCK, THREADS>>>(
        x, cent, out_map, out_rec, out_pred, n);
}